// round 7
// baseline (speedup 1.0000x reference)
#include <cuda_runtime.h>
#include <cuda_fp16.h>
#include <cstdint>

// Problem constants (fixed shapes from setup_inputs)
#define BB   16
#define NN   1536
#define CC   768
#define N0   3072
#define HH   64
#define WW   48
#define HW   (HH*WW)            // 3072
#define FM   (BB*HW*CC)         // 37,748,736 elements
#define NPTS (BB*N0)            // 49,152
#define EPSF 1e-6f

// Scratch (device globals: allocation-free, per harness rules)
__device__ __align__(16) float  g_raw [FM];      // normalized token2map map, [B][HW][C] fp32
__device__ __align__(16) __half g_cv  [FM];      // post-conv map,            [B][HW][C] fp16
__device__ __align__(16) float  g_rc  [BB*HW];   // 1/(cnt+eps), 0 for empty pixels
__device__ __align__(16) float  g_wsum[BB*NN];   // sum(agg_w) -> 1/(sum+eps)
__device__ __align__(16) float  g_wT  [9*CC];    // conv weights transposed [k][C]
__device__ int g_icnt[BB*HW];                    // per-pixel point count
__device__ int g_tcnt[BB*NN];                    // per-token point count

__device__ __forceinline__ void red_add4(float* p, float4 v) {
    asm volatile("red.global.add.v4.f32 [%0], {%1,%2,%3,%4};"
                 :: "l"(p), "f"(v.x), "f"(v.y), "f"(v.z), "f"(v.w) : "memory");
}

// pixel coords matching jnp: pos = 0.5*(clip(loc,-1,1)+1)*wh - 0.5, unfused to match rounding
__device__ __forceinline__ float pix_coord(float l, float wh) {
    l = fminf(fmaxf(l, -1.0f), 1.0f);
    float t = __fmul_rn(0.5f, __fadd_rn(l, 1.0f));
    return __fadd_rn(__fmul_rn(t, wh), -0.5f);
}

// ---------------- zero small metadata ----------------
__global__ void k_zero_meta() {
    int i = blockIdx.x * blockDim.x + threadIdx.x;
    if (i < BB*HW) g_icnt[i] = 0;
    if (i < BB*NN) { g_tcnt[i] = 0; g_wsum[i] = 0.0f; }
}

// ---------------- counts + weight sums ----------------
__global__ void k_count(const float* __restrict__ loc_orig,
                        const int*   __restrict__ idx_agg,
                        const float* __restrict__ agg_w) {
    int p = blockIdx.x * blockDim.x + threadIdx.x;
    if (p >= NPTS) return;
    int b = p / N0;
    float px = pix_coord(loc_orig[2*p],   (float)WW);
    float py = pix_coord(loc_orig[2*p+1], (float)HH);
    int ix = min(max((int)rintf(px), 0), WW-1);   // rintf = round-half-even = jnp.round
    int iy = min(max((int)rintf(py), 0), HH-1);
    atomicAdd(&g_icnt[b*HW + iy*WW + ix], 1);
    int seg = b*NN + idx_agg[p];
    atomicAdd(&g_tcnt[seg], 1);
    atomicAdd(&g_wsum[seg], agg_w[p]);
}

// ---------------- reciprocals + weight transpose ----------------
__global__ void k_prep(const float* __restrict__ conv_w) {
    int i = blockIdx.x * blockDim.x + threadIdx.x;
    if (i < 9*CC) {
        int c = i / 9, k = i % 9;           // conv_w layout [C][1][3][3]
        g_wT[k*CC + c] = conv_w[i];
    } else if (i < 9*CC + BB*HW) {
        int j = i - 9*CC;
        int n = g_icnt[j];
        g_rc[j] = (n > 0) ? 1.0f / ((float)n + EPSF) : 0.0f;
    } else if (i < 9*CC + BB*HW + BB*NN) {
        int j = i - 9*CC - BB*HW;
        g_wsum[j] = 1.0f / (g_wsum[j] + EPSF);
    }
}

// ---------------- selective zeroing: raw rows with cnt>=2, out rows with tcnt!=1 ----------------
__global__ __launch_bounds__(192) void k_zero_sel(float* __restrict__ out) {
    int bid = blockIdx.x;
    float4 z = make_float4(0.f, 0.f, 0.f, 0.f);
    if (bid < BB*HW) {
        if (__ldg(&g_icnt[bid]) >= 2)
            ((float4*)(g_raw + (size_t)bid*CC))[threadIdx.x] = z;
    } else {
        int t = bid - BB*HW;
        if (__ldg(&g_tcnt[t]) != 1)
            ((float4*)(out + (size_t)t*CC))[threadIdx.x] = z;
    }
}

// ---------------- feature scatter, pre-normalized; STG when single writer ----------------
__global__ __launch_bounds__(192) void k_scatter(const float* __restrict__ x,
                                                 const float* __restrict__ loc_orig,
                                                 const int*   __restrict__ idx_agg) {
    int p = blockIdx.x;
    int b = p / N0;
    float px = pix_coord(loc_orig[2*p],   (float)WW);
    float py = pix_coord(loc_orig[2*p+1], (float)HH);
    int ix = min(max((int)rintf(px), 0), WW-1);
    int iy = min(max((int)rintf(py), 0), HH-1);
    int pix = b*HW + iy*WW + ix;
    int tok = idx_agg[p];
    float rc = __ldg(&g_rc[pix]);            // 1/(cnt+eps)
    int cnt  = __ldg(&g_icnt[pix]);
    const float4* src = (const float4*)(x + ((size_t)b*NN + tok)*CC);
    float* dst = g_raw + (size_t)pix*CC;
    int c4 = threadIdx.x;                    // 192 threads, C/4 = 192
    float4 v = __ldg(&src[c4]);
    v.x *= rc; v.y *= rc; v.z *= rc; v.w *= rc;
    if (cnt == 1)
        ((float4*)dst)[c4] = v;
    else
        red_add4(dst + 4*c4, v);
}

// ---------------- depthwise 3x3 conv; skips empty-pixel rows entirely ----------------
__global__ __launch_bounds__(192) void k_conv(const float* __restrict__ conv_b) {
    int gp = blockIdx.x;                     // B*HW pixels
    int b  = gp / HW;
    int hw = gp - b*HW;
    int y  = hw / WW;
    int xx = hw - y*WW;
    int c4 = threadIdx.x;
    float4 acc = ((const float4*)conv_b)[c4];
    #pragma unroll
    for (int dy = -1; dy <= 1; dy++) {
        #pragma unroll
        for (int dx = -1; dx <= 1; dx++) {
            int ny = y + dy, nx = xx + dx;
            if (ny < 0 || ny >= HH || nx < 0 || nx >= WW) continue;
            int np = b*HW + ny*WW + nx;
            float rcn = __ldg(&g_rc[np]);    // 0 for empty pixel (uniform across block)
            if (rcn != 0.0f) {
                int k = (dy+1)*3 + (dx+1);
                float4 v  = *(const float4*)(g_raw + (size_t)np*CC + 4*c4);
                float4 wv = *(const float4*)(g_wT  + k*CC          + 4*c4);
                acc.x += v.x * wv.x;
                acc.y += v.y * wv.y;
                acc.z += v.z * wv.z;
                acc.w += v.w * wv.w;
            }
        }
    }
    __half2 h0 = __float22half2_rn(make_float2(acc.x, acc.y));
    __half2 h1 = __float22half2_rn(make_float2(acc.z, acc.w));
    uint2 pk;
    pk.x = *(unsigned int*)&h0;
    pk.y = *(unsigned int*)&h1;
    ((uint2*)(g_cv + (size_t)gp*CC))[c4] = pk;
}

// ---------------- bilinear gather (fp16 map) + token aggregation; STG when single ----------------
__device__ __forceinline__ float4 ld_half4(const __half* row, int c4) {
    uint2 pk = __ldg((const uint2*)row + c4);
    __half2 h0 = *(__half2*)&pk.x;
    __half2 h1 = *(__half2*)&pk.y;
    float2 f0 = __half22float2(h0);
    float2 f1 = __half22float2(h1);
    return make_float4(f0.x, f0.y, f1.x, f1.y);
}

__global__ __launch_bounds__(192) void k_gather(const float* __restrict__ loc_orig,
                                                const int*   __restrict__ idx_agg,
                                                const float* __restrict__ agg_w,
                                                float*       __restrict__ out) {
    int p = blockIdx.x;
    int b = p / N0;
    float px = pix_coord(loc_orig[2*p],   (float)WW);
    float py = pix_coord(loc_orig[2*p+1], (float)HH);
    int x0 = min(max((int)floorf(px), 0), WW-1);
    int y0 = min(max((int)floorf(py), 0), HH-1);
    int x1 = min(x0 + 1, WW-1);
    int y1 = min(y0 + 1, HH-1);
    float wx = fminf((float)x1, px) - (float)x0;   // replicates reference border quirk
    float wy = fminf((float)y1, py) - (float)y0;
    float w00 = (1.0f-wx)*(1.0f-wy);
    float w10 = wx*(1.0f-wy);
    float w01 = (1.0f-wx)*wy;
    float w11 = wx*wy;
    int base = b*HW;
    const __half* r00 = g_cv + (size_t)(base + y0*WW + x0)*CC;
    const __half* r10 = g_cv + (size_t)(base + y0*WW + x1)*CC;
    const __half* r01 = g_cv + (size_t)(base + y1*WW + x0)*CC;
    const __half* r11 = g_cv + (size_t)(base + y1*WW + x1)*CC;
    int tok = idx_agg[p];
    int seg = b*NN + tok;
    float scale = agg_w[p] * __ldg(&g_wsum[seg]);   // w / (wsum + eps)
    int tc = __ldg(&g_tcnt[seg]);
    float* dst = out + (size_t)seg*CC;
    int c4 = threadIdx.x;
    float4 a  = ld_half4(r00, c4);
    float4 bq = ld_half4(r10, c4);
    float4 cq = ld_half4(r01, c4);
    float4 dq = ld_half4(r11, c4);
    float4 v;
    v.x = (w00*a.x + w10*bq.x + w01*cq.x + w11*dq.x) * scale;
    v.y = (w00*a.y + w10*bq.y + w01*cq.y + w11*dq.y) * scale;
    v.z = (w00*a.z + w10*bq.z + w01*cq.z + w11*dq.z) * scale;
    v.w = (w00*a.w + w10*bq.w + w01*cq.w + w11*dq.w) * scale;
    if (tc == 1)
        ((float4*)dst)[c4] = v;
    else
        red_add4(dst + 4*c4, v);
}

// ---------------- launch ----------------
extern "C" void kernel_launch(void* const* d_in, const int* in_sizes, int n_in,
                              void* d_out, int out_size) {
    const float* x        = (const float*)d_in[0];
    const float* loc_orig = (const float*)d_in[2];
    const int*   idx_agg  = (const int*)  d_in[3];
    const float* agg_w    = (const float*)d_in[4];
    const float* conv_w   = (const float*)d_in[n_in-2];
    const float* conv_b   = (const float*)d_in[n_in-1];
    float* out = (float*)d_out;

    // metadata zero + counts + prep
    k_zero_meta<<<(BB*HW + 255)/256, 256>>>();
    k_count<<<(NPTS + 255)/256, 256>>>(loc_orig, idx_agg, agg_w);
    {
        int total = 9*CC + BB*HW + BB*NN;
        k_prep<<<(total + 255)/256, 256>>>(conv_w);
    }
    // selective zeroing (raw rows with cnt>=2, out rows with tcnt!=1)
    k_zero_sel<<<BB*HW + BB*NN, 192>>>(out);
    // feature scatter to map (pre-normalized)
    k_scatter<<<NPTS, 192>>>(x, loc_orig, idx_agg);
    // depthwise conv (skips empty rows), fp16 output map
    k_conv<<<BB*HW, 192>>>(conv_b);
    // bilinear gather + token aggregation
    k_gather<<<NPTS, 192>>>(loc_orig, idx_agg, agg_w, out);
}

// round 8
// speedup vs baseline: 1.0793x; 1.0793x over previous
#include <cuda_runtime.h>
#include <cuda_fp16.h>
#include <cstdint>

// Problem constants (fixed shapes from setup_inputs)
#define BB   16
#define NN   1536
#define CC   768
#define N0   3072
#define HH   64
#define WW   48
#define HW   (HH*WW)            // 3072
#define FM   (BB*HW*CC)         // 37,748,736 elements
#define NPTS (BB*N0)            // 49,152
#define EPSF 1e-6f

// Scratch (device globals: allocation-free, per harness rules)
__device__ __align__(16) float  g_raw [FM];      // normalized token2map map, [B][HW][C] fp32
__device__ __align__(16) __half g_cv  [FM];      // post-conv map,            [B][HW][C] fp16
__device__ __align__(16) float  g_rc  [BB*HW];   // 1/(cnt+eps), 0 for empty pixels
__device__ __align__(16) float  g_wsum[BB*NN];   // sum(agg_w) -> 1/(sum+eps)
__device__ __align__(16) float  g_wT  [9*CC];    // conv weights transposed [k][C]
__device__ int g_icnt[BB*HW];                    // per-pixel point count
__device__ int g_tcnt[BB*NN];                    // per-token point count

__device__ __forceinline__ void red_add4(float* p, float4 v) {
    asm volatile("red.global.add.v4.f32 [%0], {%1,%2,%3,%4};"
                 :: "l"(p), "f"(v.x), "f"(v.y), "f"(v.z), "f"(v.w) : "memory");
}

// pixel coords matching jnp: pos = 0.5*(clip(loc,-1,1)+1)*wh - 0.5, unfused to match rounding
__device__ __forceinline__ float pix_coord(float l, float wh) {
    l = fminf(fmaxf(l, -1.0f), 1.0f);
    float t = __fmul_rn(0.5f, __fadd_rn(l, 1.0f));
    return __fadd_rn(__fmul_rn(t, wh), -0.5f);
}

// ---------------- zero small metadata ----------------
__global__ void k_zero_meta() {
    int i = blockIdx.x * blockDim.x + threadIdx.x;
    if (i < BB*HW) g_icnt[i] = 0;
    if (i < BB*NN) { g_tcnt[i] = 0; g_wsum[i] = 0.0f; }
}

// ---------------- counts + weight sums ----------------
__global__ void k_count(const float* __restrict__ loc_orig,
                        const int*   __restrict__ idx_agg,
                        const float* __restrict__ agg_w) {
    int p = blockIdx.x * blockDim.x + threadIdx.x;
    if (p >= NPTS) return;
    int b = p / N0;
    float px = pix_coord(loc_orig[2*p],   (float)WW);
    float py = pix_coord(loc_orig[2*p+1], (float)HH);
    int ix = min(max((int)rintf(px), 0), WW-1);   // rintf = round-half-even = jnp.round
    int iy = min(max((int)rintf(py), 0), HH-1);
    atomicAdd(&g_icnt[b*HW + iy*WW + ix], 1);
    int seg = b*NN + idx_agg[p];
    atomicAdd(&g_tcnt[seg], 1);
    atomicAdd(&g_wsum[seg], agg_w[p]);
}

// ---------------- reciprocals + weight transpose ----------------
__global__ void k_prep(const float* __restrict__ conv_w) {
    int i = blockIdx.x * blockDim.x + threadIdx.x;
    if (i < 9*CC) {
        int c = i / 9, k = i % 9;           // conv_w layout [C][1][3][3]
        g_wT[k*CC + c] = conv_w[i];
    } else if (i < 9*CC + BB*HW) {
        int j = i - 9*CC;
        int n = g_icnt[j];
        g_rc[j] = (n > 0) ? 1.0f / ((float)n + EPSF) : 0.0f;
    } else if (i < 9*CC + BB*HW + BB*NN) {
        int j = i - 9*CC - BB*HW;
        g_wsum[j] = 1.0f / (g_wsum[j] + EPSF);
    }
}

// ---------------- selective zeroing, persistent blocks ----------------
// raw rows with cnt>=2, out rows with tcnt!=1. Grid-stride over rows;
// per-row broadcast count check, full coalesced 3 KB row write when needed.
__global__ __launch_bounds__(192) void k_zero_sel(float* __restrict__ out) {
    const int nrows = BB*HW + BB*NN;
    const int c4 = threadIdx.x;
    const float4 z = make_float4(0.f, 0.f, 0.f, 0.f);
    for (int row = blockIdx.x; row < nrows; row += gridDim.x) {
        if (row < BB*HW) {
            if (__ldg(&g_icnt[row]) >= 2)
                ((float4*)(g_raw + (size_t)row*CC))[c4] = z;
        } else {
            int t = row - BB*HW;
            if (__ldg(&g_tcnt[t]) != 1)
                ((float4*)(out + (size_t)t*CC))[c4] = z;
        }
    }
}

// ---------------- feature scatter, pre-normalized; STG when single writer ----------------
__global__ __launch_bounds__(192) void k_scatter(const float* __restrict__ x,
                                                 const float* __restrict__ loc_orig,
                                                 const int*   __restrict__ idx_agg) {
    int p = blockIdx.x;
    int b = p / N0;
    float px = pix_coord(loc_orig[2*p],   (float)WW);
    float py = pix_coord(loc_orig[2*p+1], (float)HH);
    int ix = min(max((int)rintf(px), 0), WW-1);
    int iy = min(max((int)rintf(py), 0), HH-1);
    int pix = b*HW + iy*WW + ix;
    int tok = idx_agg[p];
    float rc = __ldg(&g_rc[pix]);            // 1/(cnt+eps)
    int cnt  = __ldg(&g_icnt[pix]);
    const float4* src = (const float4*)(x + ((size_t)b*NN + tok)*CC);
    float* dst = g_raw + (size_t)pix*CC;
    int c4 = threadIdx.x;                    // 192 threads, C/4 = 192
    float4 v = __ldg(&src[c4]);
    v.x *= rc; v.y *= rc; v.z *= rc; v.w *= rc;
    if (cnt == 1)
        ((float4*)dst)[c4] = v;
    else
        red_add4(dst + 4*c4, v);
}

// ---------------- depthwise 3x3 conv; skips empty-pixel rows entirely ----------------
__global__ __launch_bounds__(192) void k_conv(const float* __restrict__ conv_b) {
    int gp = blockIdx.x;                     // B*HW pixels
    int b  = gp / HW;
    int hw = gp - b*HW;
    int y  = hw / WW;
    int xx = hw - y*WW;
    int c4 = threadIdx.x;
    float4 acc = ((const float4*)conv_b)[c4];
    #pragma unroll
    for (int dy = -1; dy <= 1; dy++) {
        #pragma unroll
        for (int dx = -1; dx <= 1; dx++) {
            int ny = y + dy, nx = xx + dx;
            if (ny < 0 || ny >= HH || nx < 0 || nx >= WW) continue;
            int np = b*HW + ny*WW + nx;
            float rcn = __ldg(&g_rc[np]);    // 0 for empty pixel (uniform across block)
            if (rcn != 0.0f) {
                int k = (dy+1)*3 + (dx+1);
                float4 v  = *(const float4*)(g_raw + (size_t)np*CC + 4*c4);
                float4 wv = *(const float4*)(g_wT  + k*CC          + 4*c4);
                acc.x += v.x * wv.x;
                acc.y += v.y * wv.y;
                acc.z += v.z * wv.z;
                acc.w += v.w * wv.w;
            }
        }
    }
    __half2 h0 = __float22half2_rn(make_float2(acc.x, acc.y));
    __half2 h1 = __float22half2_rn(make_float2(acc.z, acc.w));
    uint2 pk;
    pk.x = *(unsigned int*)&h0;
    pk.y = *(unsigned int*)&h1;
    ((uint2*)(g_cv + (size_t)gp*CC))[c4] = pk;
}

// ---------------- bilinear gather (fp16 map) + token aggregation; STG when single ----------------
__device__ __forceinline__ float4 ld_half4(const __half* row, int c4) {
    uint2 pk = __ldg((const uint2*)row + c4);
    __half2 h0 = *(__half2*)&pk.x;
    __half2 h1 = *(__half2*)&pk.y;
    float2 f0 = __half22float2(h0);
    float2 f1 = __half22float2(h1);
    return make_float4(f0.x, f0.y, f1.x, f1.y);
}

__global__ __launch_bounds__(192) void k_gather(const float* __restrict__ loc_orig,
                                                const int*   __restrict__ idx_agg,
                                                const float* __restrict__ agg_w,
                                                float*       __restrict__ out) {
    int p = blockIdx.x;
    int b = p / N0;
    float px = pix_coord(loc_orig[2*p],   (float)WW);
    float py = pix_coord(loc_orig[2*p+1], (float)HH);
    int x0 = min(max((int)floorf(px), 0), WW-1);
    int y0 = min(max((int)floorf(py), 0), HH-1);
    int x1 = min(x0 + 1, WW-1);
    int y1 = min(y0 + 1, HH-1);
    float wx = fminf((float)x1, px) - (float)x0;   // replicates reference border quirk
    float wy = fminf((float)y1, py) - (float)y0;
    float w00 = (1.0f-wx)*(1.0f-wy);
    float w10 = wx*(1.0f-wy);
    float w01 = (1.0f-wx)*wy;
    float w11 = wx*wy;
    int base = b*HW;
    const __half* r00 = g_cv + (size_t)(base + y0*WW + x0)*CC;
    const __half* r10 = g_cv + (size_t)(base + y0*WW + x1)*CC;
    const __half* r01 = g_cv + (size_t)(base + y1*WW + x0)*CC;
    const __half* r11 = g_cv + (size_t)(base + y1*WW + x1)*CC;
    int tok = idx_agg[p];
    int seg = b*NN + tok;
    float scale = agg_w[p] * __ldg(&g_wsum[seg]);   // w / (wsum + eps)
    int tc = __ldg(&g_tcnt[seg]);
    float* dst = out + (size_t)seg*CC;
    int c4 = threadIdx.x;
    float4 a  = ld_half4(r00, c4);
    float4 bq = ld_half4(r10, c4);
    float4 cq = ld_half4(r01, c4);
    float4 dq = ld_half4(r11, c4);
    float4 v;
    v.x = (w00*a.x + w10*bq.x + w01*cq.x + w11*dq.x) * scale;
    v.y = (w00*a.y + w10*bq.y + w01*cq.y + w11*dq.y) * scale;
    v.z = (w00*a.z + w10*bq.z + w01*cq.z + w11*dq.z) * scale;
    v.w = (w00*a.w + w10*bq.w + w01*cq.w + w11*dq.w) * scale;
    if (tc == 1)
        ((float4*)dst)[c4] = v;
    else
        red_add4(dst + 4*c4, v);
}

// ---------------- launch ----------------
extern "C" void kernel_launch(void* const* d_in, const int* in_sizes, int n_in,
                              void* d_out, int out_size) {
    const float* x        = (const float*)d_in[0];
    const float* loc_orig = (const float*)d_in[2];
    const int*   idx_agg  = (const int*)  d_in[3];
    const float* agg_w    = (const float*)d_in[4];
    const float* conv_w   = (const float*)d_in[n_in-2];
    const float* conv_b   = (const float*)d_in[n_in-1];
    float* out = (float*)d_out;

    // metadata zero + counts + prep
    k_zero_meta<<<(BB*HW + 255)/256, 256>>>();
    k_count<<<(NPTS + 255)/256, 256>>>(loc_orig, idx_agg, agg_w);
    {
        int total = 9*CC + BB*HW + BB*NN;
        k_prep<<<(total + 255)/256, 256>>>(conv_w);
    }
    // selective zeroing (persistent blocks, grid-stride over rows)
    k_zero_sel<<<148*20, 192>>>(out);
    // feature scatter to map (pre-normalized)
    k_scatter<<<NPTS, 192>>>(x, loc_orig, idx_agg);
    // depthwise conv (skips empty rows), fp16 output map
    k_conv<<<BB*HW, 192>>>(conv_b);
    // bilinear gather + token aggregation
    k_gather<<<NPTS, 192>>>(loc_orig, idx_agg, agg_w, out);
}

// round 9
// speedup vs baseline: 1.1332x; 1.0500x over previous
#include <cuda_runtime.h>
#include <cuda_fp16.h>
#include <cstdint>

// Problem constants (fixed shapes from setup_inputs)
#define BB   16
#define NN   1536
#define CC   768
#define N0   3072
#define HH   64
#define WW   48
#define HW   (HH*WW)            // 3072
#define FM   (BB*HW*CC)         // 37,748,736 elements
#define NPTS (BB*N0)            // 49,152
#define EPSF 1e-6f

// Scratch (device globals: allocation-free, per harness rules)
__device__ __align__(16) float  g_raw [FM];      // normalized token2map map, [B][HW][C] fp32
__device__ __align__(16) __half g_cv  [FM];      // post-conv map,            [B][HW][C] fp16
__device__ __align__(16) float  g_rc  [BB*HW];   // 1/(cnt+eps), 0 for empty pixels
__device__ __align__(16) float  g_wsum[BB*NN];   // sum(agg_w) -> 1/(sum+eps)
__device__ __align__(16) float  g_wT  [9*CC];    // conv weights transposed [k][C]
__device__ int g_icnt[BB*HW];                    // per-pixel point count
__device__ int g_tcnt[BB*NN];                    // per-token point count

__device__ __forceinline__ void red_add4(float* p, float4 v) {
    asm volatile("red.global.add.v4.f32 [%0], {%1,%2,%3,%4};"
                 :: "l"(p), "f"(v.x), "f"(v.y), "f"(v.z), "f"(v.w) : "memory");
}

// pixel coords matching jnp: pos = 0.5*(clip(loc,-1,1)+1)*wh - 0.5, unfused to match rounding
__device__ __forceinline__ float pix_coord(float l, float wh) {
    l = fminf(fmaxf(l, -1.0f), 1.0f);
    float t = __fmul_rn(0.5f, __fadd_rn(l, 1.0f));
    return __fadd_rn(__fmul_rn(t, wh), -0.5f);
}

// ---------------- zero small metadata ----------------
__global__ void k_zero_meta() {
    int i = blockIdx.x * blockDim.x + threadIdx.x;
    if (i < BB*HW) g_icnt[i] = 0;
    if (i < BB*NN) { g_tcnt[i] = 0; g_wsum[i] = 0.0f; }
}

// ---------------- counts + weight sums ----------------
__global__ void k_count(const float* __restrict__ loc_orig,
                        const int*   __restrict__ idx_agg,
                        const float* __restrict__ agg_w) {
    int p = blockIdx.x * blockDim.x + threadIdx.x;
    if (p >= NPTS) return;
    int b = p / N0;
    float px = pix_coord(loc_orig[2*p],   (float)WW);
    float py = pix_coord(loc_orig[2*p+1], (float)HH);
    int ix = min(max((int)rintf(px), 0), WW-1);   // rintf = round-half-even = jnp.round
    int iy = min(max((int)rintf(py), 0), HH-1);
    atomicAdd(&g_icnt[b*HW + iy*WW + ix], 1);
    int seg = b*NN + idx_agg[p];
    atomicAdd(&g_tcnt[seg], 1);
    atomicAdd(&g_wsum[seg], agg_w[p]);
}

// ---------------- reciprocals + weight transpose ----------------
__global__ void k_prep(const float* __restrict__ conv_w) {
    int i = blockIdx.x * blockDim.x + threadIdx.x;
    if (i < 9*CC) {
        int c = i / 9, k = i % 9;           // conv_w layout [C][1][3][3]
        g_wT[k*CC + c] = conv_w[i];
    } else if (i < 9*CC + BB*HW) {
        int j = i - 9*CC;
        int n = g_icnt[j];
        g_rc[j] = (n > 0) ? 1.0f / ((float)n + EPSF) : 0.0f;
    } else if (i < 9*CC + BB*HW + BB*NN) {
        int j = i - 9*CC - BB*HW;
        g_wsum[j] = 1.0f / (g_wsum[j] + EPSF);
    }
}

// ---------------- selective zeroing, persistent blocks, 4-row unroll ----------------
__global__ __launch_bounds__(192) void k_zero_sel(float* __restrict__ out) {
    const int nrows = BB*HW + BB*NN;
    const int c4 = threadIdx.x;
    const float4 z = make_float4(0.f, 0.f, 0.f, 0.f);
    for (int base = blockIdx.x * 4; base < nrows; base += gridDim.x * 4) {
        int need[4];
        #pragma unroll
        for (int j = 0; j < 4; j++) {
            int row = base + j;
            need[j] = 0;
            if (row < BB*HW)        need[j] = (__ldg(&g_icnt[row]) >= 2);
            else if (row < nrows)   need[j] = (__ldg(&g_tcnt[row - BB*HW]) != 1);
        }
        #pragma unroll
        for (int j = 0; j < 4; j++) {
            int row = base + j;
            if (!need[j]) continue;
            if (row < BB*HW)
                ((float4*)(g_raw + (size_t)row*CC))[c4] = z;
            else
                ((float4*)(out + (size_t)(row - BB*HW)*CC))[c4] = z;
        }
    }
}

// ---------------- feature scatter, pre-normalized; STG when single writer ----------------
__global__ __launch_bounds__(192) void k_scatter(const float* __restrict__ x,
                                                 const float* __restrict__ loc_orig,
                                                 const int*   __restrict__ idx_agg) {
    int p = blockIdx.x;
    int b = p / N0;
    float px = pix_coord(loc_orig[2*p],   (float)WW);
    float py = pix_coord(loc_orig[2*p+1], (float)HH);
    int ix = min(max((int)rintf(px), 0), WW-1);
    int iy = min(max((int)rintf(py), 0), HH-1);
    int pix = b*HW + iy*WW + ix;
    int tok = idx_agg[p];
    float rc = __ldg(&g_rc[pix]);            // 1/(cnt+eps)
    int cnt  = __ldg(&g_icnt[pix]);
    const float4* src = (const float4*)(x + ((size_t)b*NN + tok)*CC);
    float* dst = g_raw + (size_t)pix*CC;
    int c4 = threadIdx.x;                    // 192 threads, C/4 = 192
    float4 v = __ldg(&src[c4]);
    v.x *= rc; v.y *= rc; v.z *= rc; v.w *= rc;
    if (cnt == 1)
        ((float4*)dst)[c4] = v;
    else
        red_add4(dst + 4*c4, v);
}

// ---------------- row-sliding depthwise 3x3 conv ----------------
// One block per (batch, y): slide a 3x3 float4 window along x.
// Each column step loads 3 new rows (skipping empty pixels via rc smem tile).
__global__ __launch_bounds__(192) void k_conv(const float* __restrict__ conv_b) {
    __shared__ float s_rc[3][WW];
    const int by = blockIdx.x;               // b*HH + y
    const int b  = by / HH;
    const int y  = by - b*HH;
    const int tid = threadIdx.x;

    // rc masks for rows y-1..y+1 (0 outside image / empty pixel)
    for (int i = tid; i < 3*WW; i += 192) {
        int r = i / WW, xx = i - (i / WW)*WW;
        int gy = y + r - 1;
        s_rc[r][xx] = (gy >= 0 && gy < HH) ? __ldg(&g_rc[b*HW + gy*WW + xx]) : 0.0f;
    }
    __syncthreads();

    const int c4 = tid;
    float4 w[9];
    #pragma unroll
    for (int k = 0; k < 9; k++)
        w[k] = *(const float4*)(g_wT + k*CC + 4*c4);
    const float4 bias = ((const float4*)conv_b)[c4];

    const float4 z = make_float4(0.f, 0.f, 0.f, 0.f);
    // window[r][cpos]: cpos 0 = x-1, 1 = x, 2 = x+1
    float4 win[3][3];
    const size_t rowstride = (size_t)WW*CC;  // floats between vertical neighbors
    const float* base0 = g_raw + ((size_t)b*HW + (size_t)(y-1)*WW)*CC + 4*c4;

    #pragma unroll
    for (int r = 0; r < 3; r++) {
        win[r][0] = z;                       // x=-1 column
        win[r][1] = (s_rc[r][0] != 0.0f) ? *(const float4*)(base0 + r*rowstride) : z;
    }

    for (int x = 0; x < WW; x++) {
        // load column x+1
        if (x + 1 < WW) {
            #pragma unroll
            for (int r = 0; r < 3; r++)
                win[r][2] = (s_rc[r][x+1] != 0.0f)
                          ? *(const float4*)(base0 + r*rowstride + (size_t)(x+1)*CC) : z;
        } else {
            #pragma unroll
            for (int r = 0; r < 3; r++) win[r][2] = z;
        }
        // compute
        float4 acc = bias;
        #pragma unroll
        for (int r = 0; r < 3; r++) {
            #pragma unroll
            for (int cc = 0; cc < 3; cc++) {
                float4 v = win[r][cc];
                float4 wv = w[r*3 + cc];
                acc.x += v.x * wv.x;
                acc.y += v.y * wv.y;
                acc.z += v.z * wv.z;
                acc.w += v.w * wv.w;
            }
        }
        // store fp16
        __half2 h0 = __float22half2_rn(make_float2(acc.x, acc.y));
        __half2 h1 = __float22half2_rn(make_float2(acc.z, acc.w));
        uint2 pk;
        pk.x = *(unsigned int*)&h0;
        pk.y = *(unsigned int*)&h1;
        ((uint2*)(g_cv + ((size_t)b*HW + (size_t)y*WW + x)*CC))[c4] = pk;
        // shift window left
        #pragma unroll
        for (int r = 0; r < 3; r++) { win[r][0] = win[r][1]; win[r][1] = win[r][2]; }
    }
}

// ---------------- bilinear gather (fp16 map) + token aggregation; STG when single ----------------
__device__ __forceinline__ float4 ld_half4(const __half* row, int c4) {
    uint2 pk = __ldg((const uint2*)row + c4);
    __half2 h0 = *(__half2*)&pk.x;
    __half2 h1 = *(__half2*)&pk.y;
    float2 f0 = __half22float2(h0);
    float2 f1 = __half22float2(h1);
    return make_float4(f0.x, f0.y, f1.x, f1.y);
}

__global__ __launch_bounds__(192) void k_gather(const float* __restrict__ loc_orig,
                                                const int*   __restrict__ idx_agg,
                                                const float* __restrict__ agg_w,
                                                float*       __restrict__ out) {
    int p = blockIdx.x;
    int b = p / N0;
    float px = pix_coord(loc_orig[2*p],   (float)WW);
    float py = pix_coord(loc_orig[2*p+1], (float)HH);
    int x0 = min(max((int)floorf(px), 0), WW-1);
    int y0 = min(max((int)floorf(py), 0), HH-1);
    int x1 = min(x0 + 1, WW-1);
    int y1 = min(y0 + 1, HH-1);
    float wx = fminf((float)x1, px) - (float)x0;   // replicates reference border quirk
    float wy = fminf((float)y1, py) - (float)y0;
    float w00 = (1.0f-wx)*(1.0f-wy);
    float w10 = wx*(1.0f-wy);
    float w01 = (1.0f-wx)*wy;
    float w11 = wx*wy;
    int base = b*HW;
    const __half* r00 = g_cv + (size_t)(base + y0*WW + x0)*CC;
    const __half* r10 = g_cv + (size_t)(base + y0*WW + x1)*CC;
    const __half* r01 = g_cv + (size_t)(base + y1*WW + x0)*CC;
    const __half* r11 = g_cv + (size_t)(base + y1*WW + x1)*CC;
    int tok = idx_agg[p];
    int seg = b*NN + tok;
    float scale = agg_w[p] * __ldg(&g_wsum[seg]);   // w / (wsum + eps)
    int tc = __ldg(&g_tcnt[seg]);
    float* dst = out + (size_t)seg*CC;
    int c4 = threadIdx.x;
    float4 a  = ld_half4(r00, c4);
    float4 bq = ld_half4(r10, c4);
    float4 cq = ld_half4(r01, c4);
    float4 dq = ld_half4(r11, c4);
    float4 v;
    v.x = (w00*a.x + w10*bq.x + w01*cq.x + w11*dq.x) * scale;
    v.y = (w00*a.y + w10*bq.y + w01*cq.y + w11*dq.y) * scale;
    v.z = (w00*a.z + w10*bq.z + w01*cq.z + w11*dq.z) * scale;
    v.w = (w00*a.w + w10*bq.w + w01*cq.w + w11*dq.w) * scale;
    if (tc == 1)
        ((float4*)dst)[c4] = v;
    else
        red_add4(dst + 4*c4, v);
}

// ---------------- launch ----------------
extern "C" void kernel_launch(void* const* d_in, const int* in_sizes, int n_in,
                              void* d_out, int out_size) {
    const float* x        = (const float*)d_in[0];
    const float* loc_orig = (const float*)d_in[2];
    const int*   idx_agg  = (const int*)  d_in[3];
    const float* agg_w    = (const float*)d_in[4];
    const float* conv_w   = (const float*)d_in[n_in-2];
    const float* conv_b   = (const float*)d_in[n_in-1];
    float* out = (float*)d_out;

    // metadata zero + counts + prep
    k_zero_meta<<<(BB*HW + 255)/256, 256>>>();
    k_count<<<(NPTS + 255)/256, 256>>>(loc_orig, idx_agg, agg_w);
    {
        int total = 9*CC + BB*HW + BB*NN;
        k_prep<<<(total + 255)/256, 256>>>(conv_w);
    }
    // selective zeroing (persistent blocks, 4-row unroll)
    k_zero_sel<<<148*20, 192>>>(out);
    // feature scatter to map (pre-normalized)
    k_scatter<<<NPTS, 192>>>(x, loc_orig, idx_agg);
    // row-sliding depthwise conv (skips empty rows), fp16 output map
    k_conv<<<BB*HH, 192>>>(conv_b);
    // bilinear gather + token aggregation
    k_gather<<<NPTS, 192>>>(loc_orig, idx_agg, agg_w, out);
}

// round 10
// speedup vs baseline: 1.1576x; 1.0215x over previous
#include <cuda_runtime.h>
#include <cuda_fp16.h>
#include <cstdint>

// Problem constants (fixed shapes from setup_inputs)
#define BB   16
#define NN   1536
#define CC   768
#define N0   3072
#define HH   64
#define WW   48
#define HW   (HH*WW)            // 3072
#define FM   (BB*HW*CC)         // 37,748,736 elements
#define NPTS (BB*N0)            // 49,152
#define EPSF 1e-6f
#define XSEG 24                 // conv columns per block (2 segments per row)

// Scratch (device globals: allocation-free, per harness rules)
__device__ __align__(16) float  g_raw [FM];      // normalized token2map map, [B][HW][C] fp32
__device__ __align__(16) __half g_cv  [FM];      // post-conv map,            [B][HW][C] fp16
__device__ __align__(16) float  g_rc  [BB*HW];   // 1/(cnt+eps), 0 for empty pixels
__device__ __align__(16) float  g_wsum[BB*NN];   // sum(agg_w) -> 1/(sum+eps)
__device__ __align__(16) float  g_wT  [9*CC];    // conv weights transposed [k][C]
__device__ int g_icnt[BB*HW];                    // per-pixel point count
__device__ int g_tcnt[BB*NN];                    // per-token point count

__device__ __forceinline__ void red_add4(float* p, float4 v) {
    asm volatile("red.global.add.v4.f32 [%0], {%1,%2,%3,%4};"
                 :: "l"(p), "f"(v.x), "f"(v.y), "f"(v.z), "f"(v.w) : "memory");
}

// pixel coords matching jnp: pos = 0.5*(clip(loc,-1,1)+1)*wh - 0.5, unfused to match rounding
__device__ __forceinline__ float pix_coord(float l, float wh) {
    l = fminf(fmaxf(l, -1.0f), 1.0f);
    float t = __fmul_rn(0.5f, __fadd_rn(l, 1.0f));
    return __fadd_rn(__fmul_rn(t, wh), -0.5f);
}

// ---------------- zero small metadata ----------------
__global__ void k_zero_meta() {
    int i = blockIdx.x * blockDim.x + threadIdx.x;
    if (i < BB*HW) g_icnt[i] = 0;
    if (i < BB*NN) { g_tcnt[i] = 0; g_wsum[i] = 0.0f; }
}

// ---------------- counts + weight sums ----------------
__global__ void k_count(const float* __restrict__ loc_orig,
                        const int*   __restrict__ idx_agg,
                        const float* __restrict__ agg_w) {
    int p = blockIdx.x * blockDim.x + threadIdx.x;
    if (p >= NPTS) return;
    int b = p / N0;
    float px = pix_coord(loc_orig[2*p],   (float)WW);
    float py = pix_coord(loc_orig[2*p+1], (float)HH);
    int ix = min(max((int)rintf(px), 0), WW-1);   // rintf = round-half-even = jnp.round
    int iy = min(max((int)rintf(py), 0), HH-1);
    atomicAdd(&g_icnt[b*HW + iy*WW + ix], 1);
    int seg = b*NN + idx_agg[p];
    atomicAdd(&g_tcnt[seg], 1);
    atomicAdd(&g_wsum[seg], agg_w[p]);
}

// ---------------- reciprocals + weight transpose ----------------
__global__ void k_prep(const float* __restrict__ conv_w) {
    int i = blockIdx.x * blockDim.x + threadIdx.x;
    if (i < 9*CC) {
        int c = i / 9, k = i % 9;           // conv_w layout [C][1][3][3]
        g_wT[k*CC + c] = conv_w[i];
    } else if (i < 9*CC + BB*HW) {
        int j = i - 9*CC;
        int n = g_icnt[j];
        g_rc[j] = (n > 0) ? 1.0f / ((float)n + EPSF) : 0.0f;
    } else if (i < 9*CC + BB*HW + BB*NN) {
        int j = i - 9*CC - BB*HW;
        g_wsum[j] = 1.0f / (g_wsum[j] + EPSF);
    }
}

// ---------------- zero raw rows with cnt>=2 (persistent, 4-row unroll) ----------------
__global__ __launch_bounds__(192) void k_zero_raw() {
    const int c4 = threadIdx.x;
    const float4 z = make_float4(0.f, 0.f, 0.f, 0.f);
    for (int base = blockIdx.x * 4; base < BB*HW; base += gridDim.x * 4) {
        int need[4];
        #pragma unroll
        for (int j = 0; j < 4; j++)
            need[j] = (base + j < BB*HW) && (__ldg(&g_icnt[base+j]) >= 2);
        #pragma unroll
        for (int j = 0; j < 4; j++)
            if (need[j]) ((float4*)(g_raw + (size_t)(base+j)*CC))[c4] = z;
    }
}

// ---------------- zero out rows with tcnt!=1 (runs on side stream) ----------------
__global__ __launch_bounds__(192) void k_zero_out(float* __restrict__ out) {
    const int c4 = threadIdx.x;
    const float4 z = make_float4(0.f, 0.f, 0.f, 0.f);
    for (int base = blockIdx.x * 4; base < BB*NN; base += gridDim.x * 4) {
        int need[4];
        #pragma unroll
        for (int j = 0; j < 4; j++)
            need[j] = (base + j < BB*NN) && (__ldg(&g_tcnt[base+j]) != 1);
        #pragma unroll
        for (int j = 0; j < 4; j++)
            if (need[j]) ((float4*)(out + (size_t)(base+j)*CC))[c4] = z;
    }
}

// ---------------- feature scatter, pre-normalized; STG when single writer ----------------
__global__ __launch_bounds__(192) void k_scatter(const float* __restrict__ x,
                                                 const float* __restrict__ loc_orig,
                                                 const int*   __restrict__ idx_agg) {
    int p = blockIdx.x;
    int b = p / N0;
    float px = pix_coord(loc_orig[2*p],   (float)WW);
    float py = pix_coord(loc_orig[2*p+1], (float)HH);
    int ix = min(max((int)rintf(px), 0), WW-1);
    int iy = min(max((int)rintf(py), 0), HH-1);
    int pix = b*HW + iy*WW + ix;
    int tok = idx_agg[p];
    float rc = __ldg(&g_rc[pix]);            // 1/(cnt+eps)
    int cnt  = __ldg(&g_icnt[pix]);
    const float4* src = (const float4*)(x + ((size_t)b*NN + tok)*CC);
    float* dst = g_raw + (size_t)pix*CC;
    int c4 = threadIdx.x;                    // 192 threads, C/4 = 192
    float4 v = __ldg(&src[c4]);
    v.x *= rc; v.y *= rc; v.z *= rc; v.w *= rc;
    if (cnt == 1)
        ((float4*)dst)[c4] = v;
    else
        red_add4(dst + 4*c4, v);
}

// ---------------- row-sliding depthwise 3x3 conv, 2 column-segments per row ----------------
__global__ __launch_bounds__(192) void k_conv(const float* __restrict__ conv_b) {
    __shared__ float s_rc[3][WW];
    const int seg = blockIdx.x;              // 0 or 1: column segment
    const int by  = blockIdx.y;              // b*HH + y
    const int b   = by / HH;
    const int y   = by - b*HH;
    const int tid = threadIdx.x;
    const int x0  = seg * XSEG;

    // rc masks for rows y-1..y+1 (0 outside image / empty pixel), full width
    for (int i = tid; i < 3*WW; i += 192) {
        int r = i / WW, xx = i - (i / WW)*WW;
        int gy = y + r - 1;
        s_rc[r][xx] = (gy >= 0 && gy < HH) ? __ldg(&g_rc[b*HW + gy*WW + xx]) : 0.0f;
    }
    __syncthreads();

    const int c4 = tid;
    float4 w[9];
    #pragma unroll
    for (int k = 0; k < 9; k++)
        w[k] = *(const float4*)(g_wT + k*CC + 4*c4);
    const float4 bias = ((const float4*)conv_b)[c4];

    const float4 z = make_float4(0.f, 0.f, 0.f, 0.f);
    float4 win[3][3];                        // [row][cpos]: 0 = x-1, 1 = x, 2 = x+1
    const size_t rowstride = (size_t)WW*CC;
    const float* base0 = g_raw + ((size_t)b*HW + (size_t)(y-1)*WW)*CC + 4*c4;

    #pragma unroll
    for (int r = 0; r < 3; r++) {
        win[r][0] = (x0 > 0 && s_rc[r][x0-1] != 0.0f)
                  ? *(const float4*)(base0 + r*rowstride + (size_t)(x0-1)*CC) : z;
        win[r][1] = (s_rc[r][x0] != 0.0f)
                  ? *(const float4*)(base0 + r*rowstride + (size_t)x0*CC) : z;
    }

    for (int xi = 0; xi < XSEG; xi++) {
        int x = x0 + xi;
        // load column x+1
        if (x + 1 < WW) {
            #pragma unroll
            for (int r = 0; r < 3; r++)
                win[r][2] = (s_rc[r][x+1] != 0.0f)
                          ? *(const float4*)(base0 + r*rowstride + (size_t)(x+1)*CC) : z;
        } else {
            #pragma unroll
            for (int r = 0; r < 3; r++) win[r][2] = z;
        }
        // compute
        float4 acc = bias;
        #pragma unroll
        for (int r = 0; r < 3; r++) {
            #pragma unroll
            for (int cc = 0; cc < 3; cc++) {
                float4 v = win[r][cc];
                float4 wv = w[r*3 + cc];
                acc.x += v.x * wv.x;
                acc.y += v.y * wv.y;
                acc.z += v.z * wv.z;
                acc.w += v.w * wv.w;
            }
        }
        // store fp16
        __half2 h0 = __float22half2_rn(make_float2(acc.x, acc.y));
        __half2 h1 = __float22half2_rn(make_float2(acc.z, acc.w));
        uint2 pk;
        pk.x = *(unsigned int*)&h0;
        pk.y = *(unsigned int*)&h1;
        ((uint2*)(g_cv + ((size_t)b*HW + (size_t)y*WW + x)*CC))[c4] = pk;
        // shift window left
        #pragma unroll
        for (int r = 0; r < 3; r++) { win[r][0] = win[r][1]; win[r][1] = win[r][2]; }
    }
}

// ---------------- bilinear gather (fp16 map) + token aggregation; STG when single ----------------
__device__ __forceinline__ float4 ld_half4(const __half* row, int c4) {
    uint2 pk = __ldg((const uint2*)row + c4);
    __half2 h0 = *(__half2*)&pk.x;
    __half2 h1 = *(__half2*)&pk.y;
    float2 f0 = __half22float2(h0);
    float2 f1 = __half22float2(h1);
    return make_float4(f0.x, f0.y, f1.x, f1.y);
}

__global__ __launch_bounds__(192) void k_gather(const float* __restrict__ loc_orig,
                                                const int*   __restrict__ idx_agg,
                                                const float* __restrict__ agg_w,
                                                float*       __restrict__ out) {
    int p = blockIdx.x;
    int b = p / N0;
    float px = pix_coord(loc_orig[2*p],   (float)WW);
    float py = pix_coord(loc_orig[2*p+1], (float)HH);
    int x0 = min(max((int)floorf(px), 0), WW-1);
    int y0 = min(max((int)floorf(py), 0), HH-1);
    int x1 = min(x0 + 1, WW-1);
    int y1 = min(y0 + 1, HH-1);
    float wx = fminf((float)x1, px) - (float)x0;   // replicates reference border quirk
    float wy = fminf((float)y1, py) - (float)y0;
    float w00 = (1.0f-wx)*(1.0f-wy);
    float w10 = wx*(1.0f-wy);
    float w01 = (1.0f-wx)*wy;
    float w11 = wx*wy;
    int base = b*HW;
    const __half* r00 = g_cv + (size_t)(base + y0*WW + x0)*CC;
    const __half* r10 = g_cv + (size_t)(base + y0*WW + x1)*CC;
    const __half* r01 = g_cv + (size_t)(base + y1*WW + x0)*CC;
    const __half* r11 = g_cv + (size_t)(base + y1*WW + x1)*CC;
    int tok = idx_agg[p];
    int seg = b*NN + tok;
    float scale = agg_w[p] * __ldg(&g_wsum[seg]);   // w / (wsum + eps)
    int tc = __ldg(&g_tcnt[seg]);
    float* dst = out + (size_t)seg*CC;
    int c4 = threadIdx.x;
    float4 a  = ld_half4(r00, c4);
    float4 bq = ld_half4(r10, c4);
    float4 cq = ld_half4(r01, c4);
    float4 dq = ld_half4(r11, c4);
    float4 v;
    v.x = (w00*a.x + w10*bq.x + w01*cq.x + w11*dq.x) * scale;
    v.y = (w00*a.y + w10*bq.y + w01*cq.y + w11*dq.y) * scale;
    v.z = (w00*a.z + w10*bq.z + w01*cq.z + w11*dq.z) * scale;
    v.w = (w00*a.w + w10*bq.w + w01*cq.w + w11*dq.w) * scale;
    if (tc == 1)
        ((float4*)dst)[c4] = v;
    else
        red_add4(dst + 4*c4, v);
}

// ---------------- launch: fork output-zeroing onto a side stream ----------------
extern "C" void kernel_launch(void* const* d_in, const int* in_sizes, int n_in,
                              void* d_out, int out_size) {
    const float* x        = (const float*)d_in[0];
    const float* loc_orig = (const float*)d_in[2];
    const int*   idx_agg  = (const int*)  d_in[3];
    const float* agg_w    = (const float*)d_in[4];
    const float* conv_w   = (const float*)d_in[n_in-2];
    const float* conv_b   = (const float*)d_in[n_in-1];
    float* out = (float*)d_out;

    static cudaStream_t s1 = nullptr;
    static cudaEvent_t evCnt = nullptr, evOut = nullptr;
    if (!s1) {
        cudaStreamCreateWithFlags(&s1, cudaStreamNonBlocking);
        cudaEventCreateWithFlags(&evCnt, cudaEventDisableTiming);
        cudaEventCreateWithFlags(&evOut, cudaEventDisableTiming);
    }
    cudaStream_t s0 = 0;  // capture stream (legacy default joins capture)

    // setup chain on s0
    k_zero_meta<<<(BB*HW + 255)/256, 256, 0, s0>>>();
    k_count<<<(NPTS + 255)/256, 256, 0, s0>>>(loc_orig, idx_agg, agg_w);
    cudaEventRecord(evCnt, s0);

    // side stream: zero output rows (needs only counts; must finish before gather)
    cudaStreamWaitEvent(s1, evCnt, 0);
    k_zero_out<<<148*4, 192, 0, s1>>>(out);
    cudaEventRecord(evOut, s1);

    // main chain
    {
        int total = 9*CC + BB*HW + BB*NN;
        k_prep<<<(total + 255)/256, 256, 0, s0>>>(conv_w);
    }
    k_zero_raw<<<148*8, 192, 0, s0>>>();
    k_scatter<<<NPTS, 192, 0, s0>>>(x, loc_orig, idx_agg);
    {
        dim3 cgrid(WW/XSEG, BB*HH);          // 2 x 1024
        k_conv<<<cgrid, 192, 0, s0>>>(conv_b);
    }
    cudaStreamWaitEvent(s0, evOut, 0);
    k_gather<<<NPTS, 192, 0, s0>>>(loc_orig, idx_agg, agg_w, out);
}